// round 16
// baseline (speedup 1.0000x reference)
#include <cuda_runtime.h>
#include <cuda_fp16.h>
#include <cstdint>

// LSTM via mma.sync (HMMA fp16). B=65536, T=28, I=28, H=64, O=10.
// R16 = R15 (single pass: gates = Ah@Bh, K=96) retiled 4m x 4n (was 8m x 2n).
// B-fragment duplication 8x->4x: LDSM/warp/t 60->36. R12's version of this
// retile died on the 128-reg ceiling; the lo-pass removal in R14/R15 freed
// those temps, so acc=64 now fits (~110 est).
// Warp (wm 0..3, wn 0..3): rows [32wm,+32), units [16wn,+16), all 4 gates.

#define T_STEPS  28
#define I_DIM    28
#define H_DIM    64
#define O_DIM    10
#define M_TILE   128
#define NTHREADS 512
#define B_TOTAL  65536

#define KSTRIDE  104
#define ROWB     (KSTRIDE * 2)        // 208 bytes

#define A0_HI 0
#define A1_HI (A0_HI + M_TILE * ROWB)      // 26624
#define B_HI  (A1_HI + M_TILE * ROWB)      // 53248
#define WOUT  (B_HI + 256 * ROWB)          // 106496
#define BOUT  (WOUT + O_DIM * H_DIM * 4)   // 109056
#define SMEM_TOTAL (BOUT + 64)             // 109120

__device__ __forceinline__ uint32_t smem_u32(const void* p) {
    uint32_t a;
    asm("{ .reg .u64 t; cvta.to.shared.u64 t, %1; cvt.u32.u64 %0, t; }" : "=r"(a) : "l"(p));
    return a;
}

#define LDSM_X4(r, addr)                                                     \
    asm volatile("ldmatrix.sync.aligned.m8n8.x4.shared.b16 {%0,%1,%2,%3}, [%4];" \
                 : "=r"((r)[0]), "=r"((r)[1]), "=r"((r)[2]), "=r"((r)[3])    \
                 : "r"(addr))

#define MMA16816(d, a, b0v, b1v)                                             \
    asm volatile("mma.sync.aligned.m16n8k16.row.col.f32.f16.f16.f32 "       \
                 "{%0,%1,%2,%3},{%4,%5,%6,%7},{%8,%9},{%0,%1,%2,%3};"        \
                 : "+f"((d)[0]), "+f"((d)[1]), "+f"((d)[2]), "+f"((d)[3])    \
                 : "r"((a)[0]), "r"((a)[1]), "r"((a)[2]), "r"((a)[3]),       \
                   "r"(b0v), "r"(b1v))

#define QUAD_BAR(id)                                                          \
    asm volatile("bar.sync %0, 128;" :: "r"((id) + 1) : "memory")

__device__ __forceinline__ float tanha(float x) {
    float r; asm("tanh.approx.f32 %0, %1;" : "=f"(r) : "f"(x)); return r;
}
__device__ __forceinline__ float siga(float x) {
    return fmaf(tanha(0.5f * x), 0.5f, 0.5f);
}
__device__ __forceinline__ uint32_t pack_f16x2(float a, float b) {
    __half ha = __float2half_rn(a), hb = __float2half_rn(b);
    return (uint32_t)__half_as_ushort(ha) | ((uint32_t)__half_as_ushort(hb) << 16);
}

__global__ __launch_bounds__(NTHREADS, 1)
void lstm_mma_kernel(const float* __restrict__ x,
                     const float* __restrict__ W_ih,
                     const float* __restrict__ W_hh,
                     const float* __restrict__ b_ih,
                     const float* __restrict__ b_hh,
                     const float* __restrict__ W_out,
                     const float* __restrict__ b_out,
                     float* __restrict__ out)
{
    extern __shared__ char smc[];
    const uint32_t sb = smem_u32(smc);
    const int tid  = threadIdx.x;
    const int wid  = tid >> 5;
    const int lane = tid & 31;
    const int b0   = blockIdx.x * M_TILE;

    float* Wout_s = (float*)(smc + WOUT);
    float* bout_s = (float*)(smc + BOUT);

    // ---- zero A/B tiles ----
    for (int i = tid; i < (B_HI + 256 * ROWB) / 4; i += NTHREADS)
        ((uint32_t*)smc)[i] = 0u;
    __syncthreads();

    // B_HI = fp16(W): [W_hh | W_ih | bias], row n, K-major
    for (int idx = tid; idx < 256 * H_DIM; idx += NTHREADS) {
        int n = idx >> 6, k = idx & 63;
        *(__half*)(smc + B_HI + n * ROWB + k * 2) = __float2half_rn(W_hh[idx]);
    }
    for (int idx = tid; idx < 256 * I_DIM; idx += NTHREADS) {
        int n = idx / I_DIM, i = idx % I_DIM;
        *(__half*)(smc + B_HI + n * ROWB + (64 + i) * 2) = __float2half_rn(W_ih[idx]);
    }
    for (int n = tid; n < 256; n += NTHREADS)
        *(__half*)(smc + B_HI + n * ROWB + 92 * 2) = __float2half_rn(b_ih[n] + b_hh[n]);
    if (tid < M_TILE) {
        *(__half*)(smc + A0_HI + tid * ROWB + 92 * 2) = __float2half_rn(1.0f);
        *(__half*)(smc + A1_HI + tid * ROWB + 92 * 2) = __float2half_rn(1.0f);
    }
    for (int i = tid; i < O_DIM * H_DIM; i += NTHREADS) Wout_s[i] = W_out[i];
    if (tid < O_DIM) bout_s[tid] = b_out[tid];
    __syncthreads();

    // warp tiling: wm (0..3) rows [32wm,+32); wn (0..3) units [16wn,+16)
    const int wm = wid & 3;
    const int wn = wid >> 2;
    const int lg = lane >> 3, lr = lane & 7;

    const int a_row_off = ((lg & 1) * 8 + lr);
    const int a_k_off   = (lg >> 1) * 8;
    const int b_n_off   = ((lg >> 1) * 8 + lr);
    const int b_k_off   = (lg & 1) * 8;

    // c state: cs[((mt*2+rh)*2+u2)*2+e]
    float cs[16];
#pragma unroll
    for (int i = 0; i < 16; ++i) cs[i] = 0.0f;

    // x staging: group = 4 warps sharing wm (128 threads); quarter-row each.
    const int tp   = wn * 32 + lane;          // 0..127 within group
    const int xrow = wm * 32 + (tp >> 2);
    const int xq   = tp & 3;
    const float* xbase = x + (size_t)(b0 + xrow) * (T_STEPS * I_DIM) + xq * 7;

    const int ep_row_base = wm * 32 + (lane >> 2);        // + mt*16 + rh*8
    const int ep_col_base = wn * 16 + 2 * (lane & 3);     // + u2*8

    float xpre[7];
#pragma unroll
    for (int j = 0; j < 7; ++j) xpre[j] = xbase[j];

    for (int t = 0; t < T_STEPS; ++t) {
        const uint32_t curHI = sb + ((t & 1) ? A1_HI : A0_HI);
        const uint32_t nxtHI = sb + ((t & 1) ? A0_HI : A1_HI);

        // stage this thread's quarter-row of x_t
        {
            const uint32_t rbase = (uint32_t)xrow * ROWB + (64 + xq * 7) * 2;
#pragma unroll
            for (int j = 0; j < 7; ++j)
                *(__half*)(smc + (curHI - sb) + rbase + 2 * j) = __float2half_rn(xpre[j]);
            if (t + 1 < T_STEPS) {
                const float* xp = xbase + (t + 1) * I_DIM;
#pragma unroll
                for (int j = 0; j < 7; ++j) xpre[j] = xp[j];
            }
        }
        QUAD_BAR(wm);   // 4-warp scope: h(prev) + x(t) for rows of this wm

        // ---- single-phase MMA: 32 rows x 16 units x 4 gates ----
        float acc[2][2][4][4];   // [mt][u2][gate][frag]
#pragma unroll
        for (int mt = 0; mt < 2; ++mt)
#pragma unroll
            for (int u2 = 0; u2 < 2; ++u2)
#pragma unroll
                for (int g = 0; g < 4; ++g)
#pragma unroll
                    for (int r = 0; r < 4; ++r) acc[mt][u2][g][r] = 0.0f;

#pragma unroll
        for (int ks = 0; ks < 6; ++ks) {
            const int k0 = ks * 16;
            uint32_t ah[2][4];
#pragma unroll
            for (int mt = 0; mt < 2; ++mt) {
                uint32_t off = (uint32_t)(wm * 32 + mt * 16 + a_row_off) * ROWB
                             + (uint32_t)(k0 + a_k_off) * 2;
                LDSM_X4(ah[mt], curHI + off);
            }
#pragma unroll
            for (int g = 0; g < 4; ++g) {
                uint32_t off = (uint32_t)(g * 64 + wn * 16 + b_n_off) * ROWB
                             + (uint32_t)(k0 + b_k_off) * 2;
                uint32_t bh[4];
                LDSM_X4(bh, sb + B_HI + off);
#pragma unroll
                for (int mt = 0; mt < 2; ++mt)
#pragma unroll
                    for (int u2 = 0; u2 < 2; ++u2)
                        MMA16816(acc[mt][u2][g], ah[mt], bh[u2 * 2], bh[u2 * 2 + 1]);
            }
        }

        // ---- epilogue: gates -> c,h ; h into next buffer ----
#pragma unroll
        for (int mt = 0; mt < 2; ++mt)
#pragma unroll
            for (int rh = 0; rh < 2; ++rh)
#pragma unroll
                for (int u2 = 0; u2 < 2; ++u2) {
                    float hv[2];
#pragma unroll
                    for (int e = 0; e < 2; ++e) {
                        const int r = rh * 2 + e;
                        float ig = siga(acc[mt][u2][0][r]);
                        float fg = siga(acc[mt][u2][1][r]);
                        float gg = tanha(acc[mt][u2][2][r]);
                        float og = siga(acc[mt][u2][3][r]);
                        const int ci = ((mt * 2 + rh) * 2 + u2) * 2 + e;
                        float cn = fg * cs[ci] + ig * gg;
                        cs[ci] = cn;
                        hv[e] = og * tanha(cn);
                    }
                    const uint32_t off =
                        (uint32_t)(ep_row_base + mt * 16 + rh * 8) * ROWB
                      + (uint32_t)(ep_col_base + u2 * 8) * 2;
                    *(uint32_t*)(smc + (nxtHI - sb) + off) = pack_f16x2(hv[0], hv[1]);
                }
    }
    __syncthreads();   // all groups done; final h (buffer 0, T even) visible

    // ---- output projection: 4 partials per row (scratch in A1 region) ----
    float* part = (float*)(smc + A1_HI);
    {
        const int q = tid >> 7, r2 = tid & 127;
        float acc2[O_DIM];
#pragma unroll
        for (int o = 0; o < O_DIM; ++o) acc2[o] = 0.0f;
#pragma unroll
        for (int j = 0; j < 16; ++j) {
            const int u = q * 16 + j;
            float hv = __half2float(*(__half*)(smc + A0_HI + r2 * ROWB + u * 2));
#pragma unroll
            for (int o = 0; o < O_DIM; ++o)
                acc2[o] = fmaf(hv, Wout_s[o * H_DIM + u], acc2[o]);
        }
        __syncthreads();
#pragma unroll
        for (int o = 0; o < O_DIM; ++o)
            part[(q * M_TILE + r2) * O_DIM + o] = acc2[o];
    }
    __syncthreads();
    for (int idx = tid; idx < M_TILE * O_DIM; idx += NTHREADS) {
        int r = idx / O_DIM, o = idx % O_DIM;
        out[(size_t)(b0 + r) * O_DIM + o] =
            part[r * O_DIM + o] + part[(M_TILE + r) * O_DIM + o] +
            part[(2 * M_TILE + r) * O_DIM + o] + part[(3 * M_TILE + r) * O_DIM + o] +
            bout_s[o];
    }
}

extern "C" void kernel_launch(void* const* d_in, const int* in_sizes, int n_in,
                              void* d_out, int out_size)
{
    const float* x     = (const float*)d_in[0];
    const float* W_ih  = (const float*)d_in[1];
    const float* W_hh  = (const float*)d_in[2];
    const float* b_ih  = (const float*)d_in[3];
    const float* b_hh  = (const float*)d_in[4];
    const float* W_out = (const float*)d_in[5];
    const float* b_out = (const float*)d_in[6];
    float* out = (float*)d_out;

    cudaFuncSetAttribute(lstm_mma_kernel,
                         cudaFuncAttributeMaxDynamicSharedMemorySize, SMEM_TOTAL);

    lstm_mma_kernel<<<B_TOTAL / M_TILE, NTHREADS, SMEM_TOTAL>>>(
        x, W_ih, W_hh, b_ih, b_hh, W_out, b_out, out);
}

// round 17
// speedup vs baseline: 1.1688x; 1.1688x over previous
#include <cuda_runtime.h>
#include <cuda_fp16.h>
#include <cstdint>

// LSTM via mma.sync (HMMA fp16). B=65536, T=28, I=28, H=64, O=10.
// R17 = R15 split into 2 CTAs/SM: M_TILE=64, 256 threads, __launch_bounds__(256,2).
// Same per-warp tile as R15 (16 rows x 32 units, single pass Ah@Bh K=96), but
// two INDEPENDENT CTAs per SM so one CTA's MUFU epilogue overlaps the other's
// HMMA burst (R16 showed the wall is the per-CTA serial phase chain, not smem).

#define T_STEPS  28
#define I_DIM    28
#define H_DIM    64
#define O_DIM    10
#define M_TILE   64
#define NTHREADS 256
#define B_TOTAL  65536

#define KSTRIDE  104
#define ROWB     (KSTRIDE * 2)        // 208 bytes

#define A0_HI 0
#define A1_HI (A0_HI + M_TILE * ROWB)      // 13312
#define B_HI  (A1_HI + M_TILE * ROWB)      // 26624
#define WOUT  (B_HI + 256 * ROWB)          // 79872
#define BOUT  (WOUT + O_DIM * H_DIM * 4)   // 82432
#define SMEM_TOTAL (BOUT + 64)             // 82496  (x2 CTAs = 165KB <= 227KB)

__device__ __forceinline__ uint32_t smem_u32(const void* p) {
    uint32_t a;
    asm("{ .reg .u64 t; cvta.to.shared.u64 t, %1; cvt.u32.u64 %0, t; }" : "=r"(a) : "l"(p));
    return a;
}

#define LDSM_X4(r, addr)                                                     \
    asm volatile("ldmatrix.sync.aligned.m8n8.x4.shared.b16 {%0,%1,%2,%3}, [%4];" \
                 : "=r"((r)[0]), "=r"((r)[1]), "=r"((r)[2]), "=r"((r)[3])    \
                 : "r"(addr))

#define MMA16816(d, a, b0v, b1v)                                             \
    asm volatile("mma.sync.aligned.m16n8k16.row.col.f32.f16.f16.f32 "       \
                 "{%0,%1,%2,%3},{%4,%5,%6,%7},{%8,%9},{%0,%1,%2,%3};"        \
                 : "+f"((d)[0]), "+f"((d)[1]), "+f"((d)[2]), "+f"((d)[3])    \
                 : "r"((a)[0]), "r"((a)[1]), "r"((a)[2]), "r"((a)[3]),       \
                   "r"(b0v), "r"(b1v))

#define PAIR_BAR(id)                                                          \
    asm volatile("bar.sync %0, 64;" :: "r"((id) + 1) : "memory")

__device__ __forceinline__ float tanha(float x) {
    float r; asm("tanh.approx.f32 %0, %1;" : "=f"(r) : "f"(x)); return r;
}
__device__ __forceinline__ float siga(float x) {
    return fmaf(tanha(0.5f * x), 0.5f, 0.5f);
}
__device__ __forceinline__ uint32_t pack_f16x2(float a, float b) {
    __half ha = __float2half_rn(a), hb = __float2half_rn(b);
    return (uint32_t)__half_as_ushort(ha) | ((uint32_t)__half_as_ushort(hb) << 16);
}

__global__ __launch_bounds__(NTHREADS, 2)
void lstm_mma_kernel(const float* __restrict__ x,
                     const float* __restrict__ W_ih,
                     const float* __restrict__ W_hh,
                     const float* __restrict__ b_ih,
                     const float* __restrict__ b_hh,
                     const float* __restrict__ W_out,
                     const float* __restrict__ b_out,
                     float* __restrict__ out)
{
    extern __shared__ char smc[];
    const uint32_t sb = smem_u32(smc);
    const int tid  = threadIdx.x;
    const int wid  = tid >> 5;
    const int lane = tid & 31;
    const int b0   = blockIdx.x * M_TILE;

    float* Wout_s = (float*)(smc + WOUT);
    float* bout_s = (float*)(smc + BOUT);

    // ---- zero A/B tiles ----
    for (int i = tid; i < (B_HI + 256 * ROWB) / 4; i += NTHREADS)
        ((uint32_t*)smc)[i] = 0u;
    __syncthreads();

    // B_HI = fp16(W): [W_hh | W_ih | bias], row n, K-major
    for (int idx = tid; idx < 256 * H_DIM; idx += NTHREADS) {
        int n = idx >> 6, k = idx & 63;
        *(__half*)(smc + B_HI + n * ROWB + k * 2) = __float2half_rn(W_hh[idx]);
    }
    for (int idx = tid; idx < 256 * I_DIM; idx += NTHREADS) {
        int n = idx / I_DIM, i = idx % I_DIM;
        *(__half*)(smc + B_HI + n * ROWB + (64 + i) * 2) = __float2half_rn(W_ih[idx]);
    }
    for (int n = tid; n < 256; n += NTHREADS)
        *(__half*)(smc + B_HI + n * ROWB + 92 * 2) = __float2half_rn(b_ih[n] + b_hh[n]);
    if (tid < M_TILE) {
        *(__half*)(smc + A0_HI + tid * ROWB + 92 * 2) = __float2half_rn(1.0f);
        *(__half*)(smc + A1_HI + tid * ROWB + 92 * 2) = __float2half_rn(1.0f);
    }
    for (int i = tid; i < O_DIM * H_DIM; i += NTHREADS) Wout_s[i] = W_out[i];
    if (tid < O_DIM) bout_s[tid] = b_out[tid];
    __syncthreads();

    // warp tiling: wm (0..3) rows [16wm,+16); wn (0..1) units [32wn,+32)
    const int wm = wid & 3;
    const int wn = wid >> 2;
    const int lg = lane >> 3, lr = lane & 7;

    const int a_row_off = ((lg & 1) * 8 + lr);
    const int a_k_off   = (lg >> 1) * 8;
    const int b_n_off   = ((lg >> 1) * 8 + lr);
    const int b_k_off   = (lg & 1) * 8;

    float cs[16];
#pragma unroll
    for (int i = 0; i < 16; ++i) cs[i] = 0.0f;

    // pair-local x staging: group = 2 warps sharing wm (64 threads),
    // quarter-row each: row = 16wm + tp>>2, cols 64+7q..64+7q+6.
    const int tp   = wn * 32 + lane;          // 0..63 within group
    const int xrow = wm * 16 + (tp >> 2);
    const int xq   = tp & 3;
    const float* xbase = x + (size_t)(b0 + xrow) * (T_STEPS * I_DIM) + xq * 7;

    const int ep_row_base = wm * 16 + (lane >> 2);
    const int ep_col_base = wn * 32 + 2 * (lane & 3);

    float xpre[7];
#pragma unroll
    for (int j = 0; j < 7; ++j) xpre[j] = xbase[j];

    for (int t = 0; t < T_STEPS; ++t) {
        const uint32_t curHI = sb + ((t & 1) ? A1_HI : A0_HI);
        const uint32_t nxtHI = sb + ((t & 1) ? A0_HI : A1_HI);

        // stage this thread's quarter-row of x_t
        {
            const uint32_t rbase = (uint32_t)xrow * ROWB + (64 + xq * 7) * 2;
#pragma unroll
            for (int j = 0; j < 7; ++j)
                *(__half*)(smc + (curHI - sb) + rbase + 2 * j) = __float2half_rn(xpre[j]);
            if (t + 1 < T_STEPS) {
                const float* xp = xbase + (t + 1) * I_DIM;
#pragma unroll
                for (int j = 0; j < 7; ++j) xpre[j] = xp[j];
            }
        }
        PAIR_BAR(wm);   // 2-warp scope: h(prev) + x(t) for rows of this wm

        // ---- two n-half phases ----
#pragma unroll
        for (int uh = 0; uh < 2; ++uh) {
            float acc[2][4][4];
#pragma unroll
            for (int u2 = 0; u2 < 2; ++u2)
#pragma unroll
                for (int g = 0; g < 4; ++g)
#pragma unroll
                    for (int r = 0; r < 4; ++r) acc[u2][g][r] = 0.0f;

#pragma unroll
            for (int ks = 0; ks < 6; ++ks) {
                const int k0 = ks * 16;
                uint32_t ah[4];
                {
                    uint32_t off = (uint32_t)(wm * 16 + a_row_off) * ROWB
                                 + (uint32_t)(k0 + a_k_off) * 2;
                    LDSM_X4(ah, curHI + off);
                }
#pragma unroll
                for (int g = 0; g < 4; ++g) {
                    uint32_t off = (uint32_t)(g * 64 + wn * 32 + uh * 16 + b_n_off) * ROWB
                                 + (uint32_t)(k0 + b_k_off) * 2;
                    uint32_t bh[4];
                    LDSM_X4(bh, sb + B_HI + off);
#pragma unroll
                    for (int u2 = 0; u2 < 2; ++u2)
                        MMA16816(acc[u2][g], ah, bh[u2 * 2], bh[u2 * 2 + 1]);
                }
            }

            // ---- epilogue ----
#pragma unroll
            for (int rh = 0; rh < 2; ++rh)
#pragma unroll
                for (int u2 = 0; u2 < 2; ++u2) {
                    const int uj = uh * 2 + u2;
                    float hv[2];
#pragma unroll
                    for (int e = 0; e < 2; ++e) {
                        const int r = rh * 2 + e;
                        float ig = siga(acc[u2][0][r]);
                        float fg = siga(acc[u2][1][r]);
                        float gg = tanha(acc[u2][2][r]);
                        float og = siga(acc[u2][3][r]);
                        const int ci = (rh * 4 + uj) * 2 + e;
                        float cn = fg * cs[ci] + ig * gg;
                        cs[ci] = cn;
                        hv[e] = og * tanha(cn);
                    }
                    const uint32_t off =
                        (uint32_t)(ep_row_base + rh * 8) * ROWB
                      + (uint32_t)(ep_col_base + uj * 8) * 2;
                    *(uint32_t*)(smc + (nxtHI - sb) + off) = pack_f16x2(hv[0], hv[1]);
                }
        }
    }
    __syncthreads();   // all pairs done; final h (buffer 0, T even) visible

    // ---- output projection: 4 partials per row (scratch in A1 region) ----
    float* part = (float*)(smc + A1_HI);   // [4][64][10] = 10.2KB <= 13.3KB
    {
        const int q = tid >> 6, r2 = tid & 63;
        float acc[O_DIM];
#pragma unroll
        for (int o = 0; o < O_DIM; ++o) acc[o] = 0.0f;
#pragma unroll
        for (int j = 0; j < 16; ++j) {
            const int u = q * 16 + j;
            float hv = __half2float(*(__half*)(smc + A0_HI + r2 * ROWB + u * 2));
#pragma unroll
            for (int o = 0; o < O_DIM; ++o)
                acc[o] = fmaf(hv, Wout_s[o * H_DIM + u], acc[o]);
        }
        __syncthreads();
#pragma unroll
        for (int o = 0; o < O_DIM; ++o)
            part[(q * M_TILE + r2) * O_DIM + o] = acc[o];
    }
    __syncthreads();
    for (int idx = tid; idx < M_TILE * O_DIM; idx += NTHREADS) {
        int r = idx / O_DIM, o = idx % O_DIM;
        out[(size_t)(b0 + r) * O_DIM + o] =
            part[r * O_DIM + o] + part[(M_TILE + r) * O_DIM + o] +
            part[(2 * M_TILE + r) * O_DIM + o] + part[(3 * M_TILE + r) * O_DIM + o] +
            bout_s[o];
    }
}

extern "C" void kernel_launch(void* const* d_in, const int* in_sizes, int n_in,
                              void* d_out, int out_size)
{
    const float* x     = (const float*)d_in[0];
    const float* W_ih  = (const float*)d_in[1];
    const float* W_hh  = (const float*)d_in[2];
    const float* b_ih  = (const float*)d_in[3];
    const float* b_hh  = (const float*)d_in[4];
    const float* W_out = (const float*)d_in[5];
    const float* b_out = (const float*)d_in[6];
    float* out = (float*)d_out;

    cudaFuncSetAttribute(lstm_mma_kernel,
                         cudaFuncAttributeMaxDynamicSharedMemorySize, SMEM_TOTAL);

    lstm_mma_kernel<<<B_TOTAL / M_TILE, NTHREADS, SMEM_TOTAL>>>(
        x, W_ih, W_hh, b_ih, b_hh, W_out, b_out, out);
}